// round 5
// baseline (speedup 1.0000x reference)
#include <cuda_runtime.h>
#include <math.h>
#include <stdint.h>

#define HH   256
#define NN   64
#define LL   2048
#define FF   1025
#define MM   1024
#define TPB  512

// ---- f32x2 packed helpers (Blackwell) ----
__device__ __forceinline__ uint64_t pk2(float lo, float hi) {
    uint64_t r; asm("mov.b64 %0,{%1,%2};" : "=l"(r) : "f"(lo), "f"(hi)); return r;
}
__device__ __forceinline__ void up2(uint64_t v, float& lo, float& hi) {
    asm("mov.b64 {%0,%1},%2;" : "=f"(lo), "=f"(hi) : "l"(v));
}
__device__ __forceinline__ uint64_t sub2(uint64_t a, uint64_t b) {
    uint64_t d; asm("sub.rn.f32x2 %0,%1,%2;" : "=l"(d) : "l"(a), "l"(b)); return d;
}
__device__ __forceinline__ uint64_t mul2(uint64_t a, uint64_t b) {
    uint64_t d; asm("mul.rn.f32x2 %0,%1,%2;" : "=l"(d) : "l"(a), "l"(b)); return d;
}
__device__ __forceinline__ uint64_t fma2(uint64_t a, uint64_t b, uint64_t c) {
    uint64_t d; asm("fma.rn.f32x2 %0,%1,%2,%3;" : "=l"(d) : "l"(a), "l"(b), "l"(c)); return d;
}
__device__ __forceinline__ uint64_t rcp2(uint64_t v) {
    float lo, hi; up2(v, lo, hi);
    float a, b;
    asm("rcp.approx.f32 %0,%1;" : "=f"(a) : "f"(lo));
    asm("rcp.approx.f32 %0,%1;" : "=f"(b) : "f"(hi));
    return pk2(a, b);
}
__device__ __forceinline__ float lanesum(uint64_t v) {
    float lo, hi; up2(v, lo, hi); return lo + hi;
}

// Woodbury + bilinear gain epilogue for one frequency -> X in smem
__device__ __forceinline__ void woodbury(float A00r, float A00i, float A01r, float A01i,
                                         float A10r, float A10i, float A11r, float A11i,
                                         float dt, float gi, int f,
                                         float* __restrict__ Xr, float* __restrict__ Xi) {
    float r00r = dt * A00r, r00i = dt * A00i;
    float r01r = dt * A01r, r01i = dt * A01i;
    float r10r = dt * A10r, r10i = dt * A10i;
    float r11r = dt * A11r, r11i = dt * A11i;
    float numr = r01r * r10r - r01i * r10i;
    float numi = r01r * r10i + r01i * r10r;
    float denr = 1.0f + r11r;
    float deni = r11i;
    float dd   = denr * denr + deni * deni;
    float dinv; asm("rcp.approx.f32 %0,%1;" : "=f"(dinv) : "f"(dd));
    float qr = (numr * denr + numi * deni) * dinv;
    float qi = (numi * denr - numr * deni) * dinv;
    float xr = r00r - qr;
    float xi = r00i - qi;
    Xr[f] = xr - xi * gi;      // * (1 + i*gi), gi = tan(pi f / L)
    Xi[f] = xr * gi + xi;
}

// ---------------------------------------------------------------------------
// Fused kernel, one block per h, 512 threads (16 warps -> 2 blocks/SM resident).
// Phase 1: Cauchy + Woodbury. f32x2 lanes = (n, n+1); each thread owns the
//   2 frequencies {tid, tid+512}. Imaginary sums accumulated NEGATED against
//   pre-negated constants (no sign-flip ops in the hot loop).
// Phase 2: irfft(L=2048) via 1024-pt complex inverse FFT, smem twiddle table.
// ---------------------------------------------------------------------------
__global__ __launch_bounds__(TPB, 2)
void fused_kernel(const float* __restrict__ Cin, const float* __restrict__ Bin,
                  const float* __restrict__ Pin, const float* __restrict__ Win,
                  const float* __restrict__ logdt, float* __restrict__ out) {
    // [const][n]: 0 wdi, 1 wdr2, 2 -wdr, 3 v00r, 4 v00i, 5 -v00i,
    //             6 v01r, 7 v01i, 8 -v01i, 9 v10r, 10 v10i, 11 -v10i, 12 v11r
    __shared__ __align__(16) float scn[13][NN];
    __shared__ float2 tw[MM / 2];          // e^{+2*pi*i*t/1024}, t in [0,512)
    __shared__ float Xr[FF + 3], Xi[FF + 3];
    __shared__ float Zr[MM], Zi[MM];

    const int h   = blockIdx.x;
    const int tid = threadIdx.x;
    const float dt = expf(logdt[h]);

    // twiddle table: one entry per thread
    {
        float s, c;
        sincospif((float)tid * (1.0f / 512.0f), &s, &c);   // e^{i*pi*tid/512}
        tw[tid] = make_float2(c, s);
    }

    if (tid < NN) {
        const int base = h * (NN * 2) + tid * 2;
        float cr = Cin[base], ci = Cin[base + 1];
        float br = Bin[base], bi = Bin[base + 1];
        float pr = Pin[base], pi = Pin[base + 1];
        float wr = Win[base], wi = Win[base + 1];
        float wdr = wr * dt, wdi = wi * dt;
        float v00r = br * cr - bi * ci, v00i = br * ci + bi * cr;   // B*C
        float v01r = br * pr + bi * pi, v01i = bi * pr - br * pi;   // B*conj(P)
        float v10r = pr * cr - pi * ci, v10i = pr * ci + pi * cr;   // P*C
        scn[0][tid]  = wdi;
        scn[1][tid]  = wdr * wdr;
        scn[2][tid]  = -wdr;
        scn[3][tid]  = v00r;
        scn[4][tid]  = v00i;
        scn[5][tid]  = -v00i;
        scn[6][tid]  = v01r;
        scn[7][tid]  = v01i;
        scn[8][tid]  = -v01i;
        scn[9][tid]  = v10r;
        scn[10][tid] = v10i;
        scn[11][tid] = -v10i;
        scn[12][tid] = pr * pr + pi * pi;   // v11r = |P|^2 (real)
    }
    __syncthreads();

    // z_f = 2*i*tan(pi f / L); this thread's 2 freqs, duplicated into lanes
    float zis[2];
    uint64_t zi[2];
#pragma unroll
    for (int j = 0; j < 2; j++) {
        int f = tid + 512 * j;
        float s, c;
        sincospif((float)f * (1.0f / LL), &s, &c);
        zis[j] = 2.0f * __fdividef(s, c);
        zi[j] = pk2(zis[j], zis[j]);
    }

    // accumulators: r sums real, iN sums NEGATED imag
    uint64_t a00r[2] = {0, 0}, a00iN[2] = {0, 0};
    uint64_t a01r[2] = {0, 0}, a01iN[2] = {0, 0};
    uint64_t a10r[2] = {0, 0}, a10iN[2] = {0, 0};
    uint64_t a11r[2] = {0, 0}, a11iN[2] = {0, 0};

    const uint64_t* s0  = (const uint64_t*)&scn[0][0];
    const uint64_t* s1  = (const uint64_t*)&scn[1][0];
    const uint64_t* s2  = (const uint64_t*)&scn[2][0];
    const uint64_t* s3  = (const uint64_t*)&scn[3][0];
    const uint64_t* s4  = (const uint64_t*)&scn[4][0];
    const uint64_t* s5  = (const uint64_t*)&scn[5][0];
    const uint64_t* s6  = (const uint64_t*)&scn[6][0];
    const uint64_t* s7  = (const uint64_t*)&scn[7][0];
    const uint64_t* s8  = (const uint64_t*)&scn[8][0];
    const uint64_t* s9  = (const uint64_t*)&scn[9][0];
    const uint64_t* s10 = (const uint64_t*)&scn[10][0];
    const uint64_t* s11 = (const uint64_t*)&scn[11][0];
    const uint64_t* s12 = (const uint64_t*)&scn[12][0];

#pragma unroll 2
    for (int m = 0; m < NN / 2; m++) {       // n-pair index
        uint64_t wdi = s0[m], wdr2 = s1[m], nwdr = s2[m];
        uint64_t tr[2], mti[2];
#pragma unroll
        for (int j = 0; j < 2; j++) {
            // denom = -wdr + i*(zi - wdi); 1/denom = (-wdr - i*D)*inv
            uint64_t D   = sub2(zi[j], wdi);
            uint64_t den = fma2(D, D, wdr2);
            uint64_t inv = rcp2(den);
            tr[j]  = mul2(nwdr, inv);        //  Re 1/denom
            mti[j] = mul2(D, inv);           // -Im 1/denom
        }
        {
            uint64_t vr = s3[m], vi = s4[m], nvi = s5[m];
#pragma unroll
            for (int j = 0; j < 2; j++) {
                a00r[j]  = fma2(vi,  mti[j], a00r[j]);  a00r[j]  = fma2(vr, tr[j], a00r[j]);
                a00iN[j] = fma2(vr,  mti[j], a00iN[j]); a00iN[j] = fma2(nvi, tr[j], a00iN[j]);
            }
        }
        {
            uint64_t vr = s6[m], vi = s7[m], nvi = s8[m];
#pragma unroll
            for (int j = 0; j < 2; j++) {
                a01r[j]  = fma2(vi,  mti[j], a01r[j]);  a01r[j]  = fma2(vr, tr[j], a01r[j]);
                a01iN[j] = fma2(vr,  mti[j], a01iN[j]); a01iN[j] = fma2(nvi, tr[j], a01iN[j]);
            }
        }
        {
            uint64_t vr = s9[m], vi = s10[m], nvi = s11[m];
#pragma unroll
            for (int j = 0; j < 2; j++) {
                a10r[j]  = fma2(vi,  mti[j], a10r[j]);  a10r[j]  = fma2(vr, tr[j], a10r[j]);
                a10iN[j] = fma2(vr,  mti[j], a10iN[j]); a10iN[j] = fma2(nvi, tr[j], a10iN[j]);
            }
        }
        {
            uint64_t vr = s12[m];
#pragma unroll
            for (int j = 0; j < 2; j++) {
                a11r[j]  = fma2(vr, tr[j],  a11r[j]);
                a11iN[j] = fma2(vr, mti[j], a11iN[j]);
            }
        }
    }

    // Epilogue: lane-sum (over n halves), un-negate imag, Woodbury, gain
#pragma unroll
    for (int j = 0; j < 2; j++) {
        int f = tid + 512 * j;
        woodbury(lanesum(a00r[j]), -lanesum(a00iN[j]),
                 lanesum(a01r[j]), -lanesum(a01iN[j]),
                 lanesum(a10r[j]), -lanesum(a10iN[j]),
                 lanesum(a11r[j]), -lanesum(a11iN[j]),
                 dt, 0.5f * zis[j], f, Xr, Xi);
    }

    // Nyquist bin f = L/2 (removable singularity): limit = 0.5*dt*sum_n v00r
    if (tid == 0) {
        float sr = 0.f;
        for (int n = 0; n < NN; n++) sr += scn[3][n];
        Xr[MM] = 0.5f * dt * sr;
        Xi[MM] = 0.f;
    }
    __syncthreads();

    // ---- Phase 2: irfft via 1024-pt complex inverse FFT ----
    const float scl = 1.0f / 2048.0f;
#pragma unroll
    for (int j = 0; j < 2; j++) {
        int k = tid + 512 * j;
        float Xkx = Xr[k],      Xky = Xi[k];
        float Xmx = Xr[MM - k], Xmy = Xi[MM - k];
        if (k == 0) { Xky = 0.f; Xmy = 0.f; }   // drop imag of DC & Nyquist
        float er  = (Xkx + Xmx) * scl;
        float ei  = (Xky - Xmy) * scl;
        float pr  = (Xkx - Xmx) * scl;
        float pi_ = (Xky + Xmy) * scl;
        float s, c;
        sincospif((float)k * (1.0f / MM), &s, &c);  // e^{+i*pi*k/1024}
        float Or = pr * c - pi_ * s;
        float Oi = pr * s + pi_ * c;
        Zr[k] = er - Oi;            // Z = E + i*O
        Zi[k] = ei + Or;
    }
    __syncthreads();

    // 512 butterflies per stage, one per thread; twiddles from table
    for (int half = MM / 2; half >= 1; half >>= 1) {
        const int tmul = (MM / 2) / half;
        int jj = tid & (half - 1);
        int i0 = ((tid - jj) << 1) + jj;
        int i1 = i0 + half;
        float ar = Zr[i0], ai = Zi[i0];
        float br = Zr[i1], bi = Zi[i1];
        float sr = ar + br, si = ai + bi;
        float dr = ar - br, di = ai - bi;
        float2 w = tw[jj * tmul];               // e^{+2pi i (jj*tmul)/1024}
        Zr[i0] = sr; Zi[i0] = si;
        Zr[i1] = dr * w.x - di * w.y;
        Zi[i1] = dr * w.y + di * w.x;
        __syncthreads();
    }

    float2* out2 = reinterpret_cast<float2*>(out + h * LL);
#pragma unroll
    for (int j = 0; j < 2; j++) {
        int p = tid + 512 * j;
        int n = __brev((unsigned)p) >> 22;   // 10-bit reverse
        out2[n] = make_float2(Zr[p], Zi[p]);
    }
}

extern "C" void kernel_launch(void* const* d_in, const int* in_sizes, int n_in,
                              void* d_out, int out_size) {
    (void)in_sizes; (void)n_in; (void)out_size;
    const float* C  = (const float*)d_in[0];
    const float* B  = (const float*)d_in[1];
    const float* P  = (const float*)d_in[2];
    const float* W  = (const float*)d_in[3];
    const float* ld = (const float*)d_in[4];
    fused_kernel<<<HH, TPB>>>(C, B, P, W, ld, (float*)d_out);
}

// round 7
// speedup vs baseline: 1.8863x; 1.8863x over previous
#include <cuda_runtime.h>
#include <math.h>
#include <stdint.h>

#define HH   256
#define NN   64
#define LL   2048
#define FF   1025
#define MM   1024

// frequency-domain kernel k_f: (H, F) complex
__device__ float2 g_kf[HH * FF];

// ---- f32x2 packed helpers (Blackwell) ----
__device__ __forceinline__ uint64_t pk2(float lo, float hi) {
    uint64_t r; asm("mov.b64 %0,{%1,%2};" : "=l"(r) : "f"(lo), "f"(hi)); return r;
}
__device__ __forceinline__ void up2(uint64_t v, float& lo, float& hi) {
    asm("mov.b64 {%0,%1},%2;" : "=f"(lo), "=f"(hi) : "l"(v));
}
__device__ __forceinline__ uint64_t sub2(uint64_t a, uint64_t b) {
    uint64_t d; asm("sub.rn.f32x2 %0,%1,%2;" : "=l"(d) : "l"(a), "l"(b)); return d;
}
__device__ __forceinline__ uint64_t mul2(uint64_t a, uint64_t b) {
    uint64_t d; asm("mul.rn.f32x2 %0,%1,%2;" : "=l"(d) : "l"(a), "l"(b)); return d;
}
__device__ __forceinline__ uint64_t fma2(uint64_t a, uint64_t b, uint64_t c) {
    uint64_t d; asm("fma.rn.f32x2 %0,%1,%2,%3;" : "=l"(d) : "l"(a), "l"(b), "l"(c)); return d;
}
__device__ __forceinline__ uint64_t rcp2(uint64_t v) {
    float lo, hi; up2(v, lo, hi);
    float a, b;
    asm("rcp.approx.f32 %0,%1;" : "=f"(a) : "f"(lo));
    asm("rcp.approx.f32 %0,%1;" : "=f"(b) : "f"(hi));
    return pk2(a, b);
}
__device__ __forceinline__ float lanesum(uint64_t v) {
    float lo, hi; up2(v, lo, hi); return lo + hi;
}

// Woodbury + bilinear gain epilogue for one frequency -> g_kf
__device__ __forceinline__ void woodbury(float A00r, float A00i, float A01r, float A01i,
                                         float A10r, float A10i, float A11r, float A11i,
                                         float dt, float gi, float2* __restrict__ dst) {
    float r00r = dt * A00r, r00i = dt * A00i;
    float r01r = dt * A01r, r01i = dt * A01i;
    float r10r = dt * A10r, r10i = dt * A10i;
    float r11r = dt * A11r, r11i = dt * A11i;
    float numr = r01r * r10r - r01i * r10i;
    float numi = r01r * r10i + r01i * r10r;
    float denr = 1.0f + r11r;
    float deni = r11i;
    float dd   = denr * denr + deni * deni;
    float dinv; asm("rcp.approx.f32 %0,%1;" : "=f"(dinv) : "f"(dd));
    float qr = (numr * denr + numi * deni) * dinv;
    float qi = (numi * denr - numr * deni) * dinv;
    float xr = r00r - qr;
    float xi = r00i - qi;
    *dst = make_float2(xr - xi * gi, xr * gi + xi);   // * (1 + i*gi)
}

// ---------------------------------------------------------------------------
// Kernel 1: Cauchy + Woodbury -> g_kf.
// Grid 512: blockIdx = h*2 + slice (slice = 512-freq half). 256 threads,
// 2 freqs/thread (f = slice*512 + tid + 256j). f32x2 lanes = (n, n+1) pair.
// Imag sums accumulated NEGATED against pre-negated constants.
// ---------------------------------------------------------------------------
__global__ __launch_bounds__(256)
void cauchy_kernel(const float* __restrict__ Cin, const float* __restrict__ Bin,
                   const float* __restrict__ Pin, const float* __restrict__ Win,
                   const float* __restrict__ logdt) {
    // [const][n]: 0 wdi, 1 wdr2, 2 -wdr, 3 v00r, 4 v00i, 5 -v00i,
    //             6 v01r, 7 v01i, 8 -v01i, 9 v10r, 10 v10i, 11 -v10i, 12 v11r
    __shared__ __align__(16) float scn[13][NN];

    const int h     = blockIdx.x >> 1;
    const int slice = blockIdx.x & 1;
    const int tid   = threadIdx.x;
    const float dt  = expf(logdt[h]);

    if (tid < NN) {
        const int base = h * (NN * 2) + tid * 2;
        float cr = Cin[base], ci = Cin[base + 1];
        float br = Bin[base], bi = Bin[base + 1];
        float pr = Pin[base], pi = Pin[base + 1];
        float wr = Win[base], wi = Win[base + 1];
        float wdr = wr * dt, wdi = wi * dt;
        float v00r = br * cr - bi * ci, v00i = br * ci + bi * cr;   // B*C
        float v01r = br * pr + bi * pi, v01i = bi * pr - br * pi;   // B*conj(P)
        float v10r = pr * cr - pi * ci, v10i = pr * ci + pi * cr;   // P*C
        scn[0][tid]  = wdi;
        scn[1][tid]  = wdr * wdr;
        scn[2][tid]  = -wdr;
        scn[3][tid]  = v00r;
        scn[4][tid]  = v00i;
        scn[5][tid]  = -v00i;
        scn[6][tid]  = v01r;
        scn[7][tid]  = v01i;
        scn[8][tid]  = -v01i;
        scn[9][tid]  = v10r;
        scn[10][tid] = v10i;
        scn[11][tid] = -v10i;
        scn[12][tid] = pr * pr + pi * pi;   // v11r = |P|^2 (real)
    }
    __syncthreads();

    // z_f = 2*i*tan(pi f / L); this thread's 2 freqs, duplicated into lanes
    const int fbase = slice * 512 + tid;
    float zis[2];
    uint64_t zi[2];
#pragma unroll
    for (int j = 0; j < 2; j++) {
        int f = fbase + 256 * j;
        float s, c;
        sincospif((float)f * (1.0f / LL), &s, &c);
        zis[j] = 2.0f * __fdividef(s, c);
        zi[j] = pk2(zis[j], zis[j]);
    }

    uint64_t a00r[2] = {0, 0}, a00iN[2] = {0, 0};
    uint64_t a01r[2] = {0, 0}, a01iN[2] = {0, 0};
    uint64_t a10r[2] = {0, 0}, a10iN[2] = {0, 0};
    uint64_t a11r[2] = {0, 0}, a11iN[2] = {0, 0};

    const uint64_t* s0  = (const uint64_t*)&scn[0][0];
    const uint64_t* s1  = (const uint64_t*)&scn[1][0];
    const uint64_t* s2  = (const uint64_t*)&scn[2][0];
    const uint64_t* s3  = (const uint64_t*)&scn[3][0];
    const uint64_t* s4  = (const uint64_t*)&scn[4][0];
    const uint64_t* s5  = (const uint64_t*)&scn[5][0];
    const uint64_t* s6  = (const uint64_t*)&scn[6][0];
    const uint64_t* s7  = (const uint64_t*)&scn[7][0];
    const uint64_t* s8  = (const uint64_t*)&scn[8][0];
    const uint64_t* s9  = (const uint64_t*)&scn[9][0];
    const uint64_t* s10 = (const uint64_t*)&scn[10][0];
    const uint64_t* s11 = (const uint64_t*)&scn[11][0];
    const uint64_t* s12 = (const uint64_t*)&scn[12][0];

#pragma unroll 2
    for (int m = 0; m < NN / 2; m++) {       // n-pair index
        uint64_t wdi = s0[m], wdr2 = s1[m], nwdr = s2[m];
        uint64_t tr[2], mti[2];
#pragma unroll
        for (int j = 0; j < 2; j++) {
            uint64_t D   = sub2(zi[j], wdi);
            uint64_t den = fma2(D, D, wdr2);
            uint64_t inv = rcp2(den);
            tr[j]  = mul2(nwdr, inv);        //  Re 1/denom
            mti[j] = mul2(D, inv);           // -Im 1/denom
        }
        {
            uint64_t vr = s3[m], vi = s4[m], nvi = s5[m];
#pragma unroll
            for (int j = 0; j < 2; j++) {
                a00r[j]  = fma2(vi,  mti[j], a00r[j]);  a00r[j]  = fma2(vr,  tr[j], a00r[j]);
                a00iN[j] = fma2(vr,  mti[j], a00iN[j]); a00iN[j] = fma2(nvi, tr[j], a00iN[j]);
            }
        }
        {
            uint64_t vr = s6[m], vi = s7[m], nvi = s8[m];
#pragma unroll
            for (int j = 0; j < 2; j++) {
                a01r[j]  = fma2(vi,  mti[j], a01r[j]);  a01r[j]  = fma2(vr,  tr[j], a01r[j]);
                a01iN[j] = fma2(vr,  mti[j], a01iN[j]); a01iN[j] = fma2(nvi, tr[j], a01iN[j]);
            }
        }
        {
            uint64_t vr = s9[m], vi = s10[m], nvi = s11[m];
#pragma unroll
            for (int j = 0; j < 2; j++) {
                a10r[j]  = fma2(vi,  mti[j], a10r[j]);  a10r[j]  = fma2(vr,  tr[j], a10r[j]);
                a10iN[j] = fma2(vr,  mti[j], a10iN[j]); a10iN[j] = fma2(nvi, tr[j], a10iN[j]);
            }
        }
        {
            uint64_t vr = s12[m];
#pragma unroll
            for (int j = 0; j < 2; j++) {
                a11r[j]  = fma2(vr, tr[j],  a11r[j]);
                a11iN[j] = fma2(vr, mti[j], a11iN[j]);
            }
        }
    }

    float2* kf = g_kf + h * FF;
#pragma unroll
    for (int j = 0; j < 2; j++) {
        int f = fbase + 256 * j;
        woodbury(lanesum(a00r[j]), -lanesum(a00iN[j]),
                 lanesum(a01r[j]), -lanesum(a01iN[j]),
                 lanesum(a10r[j]), -lanesum(a10iN[j]),
                 lanesum(a11r[j]), -lanesum(a11iN[j]),
                 dt, 0.5f * zis[j], kf + f);
    }

    // Nyquist bin f = L/2 (removable singularity): limit = 0.5*dt*sum_n v00r
    if (slice == 1 && tid == 0) {
        float sr = 0.f;
        for (int n = 0; n < NN; n++) sr += scn[3][n];
        kf[MM] = make_float2(0.5f * dt * sr, 0.f);
    }
}

// ---------------------------------------------------------------------------
// Kernel 2: irfft(L=2048) per h via 1024-pt complex inverse FFT.
// 512 threads: one butterfly per thread per stage; smem twiddle table.
// ---------------------------------------------------------------------------
__global__ __launch_bounds__(512)
void ifft_kernel(float* __restrict__ out) {
    __shared__ float Xr[FF + 3], Xi[FF + 3];
    __shared__ float Zr[MM], Zi[MM];
    __shared__ float2 tw[MM / 2];          // e^{+2*pi*i*t/1024}

    const int h   = blockIdx.x;
    const int tid = threadIdx.x;
    const float2* kf = g_kf + h * FF;

    {   // twiddle table: one entry per thread
        float s, c;
        sincospif((float)tid * (1.0f / 512.0f), &s, &c);
        tw[tid] = make_float2(c, s);
    }
#pragma unroll
    for (int j = 0; j < 2; j++) {
        int k = tid + 512 * j;
        float2 v = kf[k];
        Xr[k] = v.x; Xi[k] = v.y;
    }
    if (tid == 0) { float2 v = kf[MM]; Xr[MM] = v.x; Xi[MM] = v.y; }
    __syncthreads();

    const float scl = 1.0f / 2048.0f;
#pragma unroll
    for (int j = 0; j < 2; j++) {
        int k = tid + 512 * j;
        float Xkx = Xr[k],      Xky = Xi[k];
        float Xmx = Xr[MM - k], Xmy = Xi[MM - k];
        if (k == 0) { Xky = 0.f; Xmy = 0.f; }   // drop imag of DC & Nyquist
        float er  = (Xkx + Xmx) * scl;
        float ei  = (Xky - Xmy) * scl;
        float pr  = (Xkx - Xmx) * scl;
        float pi_ = (Xky + Xmy) * scl;
        float s, c;
        sincospif((float)k * (1.0f / MM), &s, &c);  // e^{+i*pi*k/1024}
        float Or = pr * c - pi_ * s;
        float Oi = pr * s + pi_ * c;
        Zr[k] = er - Oi;            // Z = E + i*O
        Zi[k] = ei + Or;
    }
    __syncthreads();

    for (int half = MM / 2; half >= 1; half >>= 1) {
        const int tmul = (MM / 2) / half;
        int jj = tid & (half - 1);
        int i0 = ((tid - jj) << 1) + jj;
        int i1 = i0 + half;
        float ar = Zr[i0], ai = Zi[i0];
        float br = Zr[i1], bi = Zi[i1];
        float sr = ar + br, si = ai + bi;
        float dr = ar - br, di = ai - bi;
        float2 w = tw[jj * tmul];               // e^{+2pi i (jj*tmul)/1024}
        Zr[i0] = sr; Zi[i0] = si;
        Zr[i1] = dr * w.x - di * w.y;
        Zi[i1] = dr * w.y + di * w.x;
        __syncthreads();
    }

    float2* out2 = reinterpret_cast<float2*>(out + h * LL);
#pragma unroll
    for (int j = 0; j < 2; j++) {
        int p = tid + 512 * j;
        int n = __brev((unsigned)p) >> 22;   // 10-bit reverse
        out2[n] = make_float2(Zr[p], Zi[p]);
    }
}

extern "C" void kernel_launch(void* const* d_in, const int* in_sizes, int n_in,
                              void* d_out, int out_size) {
    (void)in_sizes; (void)n_in; (void)out_size;
    const float* C  = (const float*)d_in[0];
    const float* B  = (const float*)d_in[1];
    const float* P  = (const float*)d_in[2];
    const float* W  = (const float*)d_in[3];
    const float* ld = (const float*)d_in[4];
    cauchy_kernel<<<HH * 2, 256>>>(C, B, P, W, ld);
    ifft_kernel<<<HH, 512>>>((float*)d_out);
}

// round 8
// speedup vs baseline: 2.1358x; 1.1322x over previous
#include <cuda_runtime.h>
#include <math.h>
#include <stdint.h>

#define HH   256
#define NN   64
#define LL   2048
#define FF   1025
#define MM   1024
#define TPB  256

// ---- f32x2 packed helpers (Blackwell) ----
__device__ __forceinline__ uint64_t pk2(float lo, float hi) {
    uint64_t r; asm("mov.b64 %0,{%1,%2};" : "=l"(r) : "f"(lo), "f"(hi)); return r;
}
__device__ __forceinline__ void up2(uint64_t v, float& lo, float& hi) {
    asm("mov.b64 {%0,%1},%2;" : "=f"(lo), "=f"(hi) : "l"(v));
}
__device__ __forceinline__ uint64_t sub2(uint64_t a, uint64_t b) {
    uint64_t d; asm("sub.rn.f32x2 %0,%1,%2;" : "=l"(d) : "l"(a), "l"(b)); return d;
}
__device__ __forceinline__ uint64_t mul2(uint64_t a, uint64_t b) {
    uint64_t d; asm("mul.rn.f32x2 %0,%1,%2;" : "=l"(d) : "l"(a), "l"(b)); return d;
}
__device__ __forceinline__ uint64_t fma2(uint64_t a, uint64_t b, uint64_t c) {
    uint64_t d; asm("fma.rn.f32x2 %0,%1,%2,%3;" : "=l"(d) : "l"(a), "l"(b), "l"(c)); return d;
}
__device__ __forceinline__ uint64_t rcp2(uint64_t v) {
    float lo, hi; up2(v, lo, hi);
    float a, b;
    asm("rcp.approx.f32 %0,%1;" : "=f"(a) : "f"(lo));
    asm("rcp.approx.f32 %0,%1;" : "=f"(b) : "f"(hi));
    return pk2(a, b);
}
__device__ __forceinline__ float lanesum(uint64_t v) {
    float lo, hi; up2(v, lo, hi); return lo + hi;
}

// complex helpers on float2
__device__ __forceinline__ float2 cadd(float2 a, float2 b) { return make_float2(a.x + b.x, a.y + b.y); }
__device__ __forceinline__ float2 csub(float2 a, float2 b) { return make_float2(a.x - b.x, a.y - b.y); }
__device__ __forceinline__ float2 cmul(float2 a, float2 w) {
    return make_float2(a.x * w.x - a.y * w.y, a.x * w.y + a.y * w.x);
}

// Woodbury + bilinear gain epilogue for one frequency -> X in smem
__device__ __forceinline__ void woodbury(float A00r, float A00i, float A01r, float A01i,
                                         float A10r, float A10i, float A11r, float A11i,
                                         float dt, float gi, int f,
                                         float* __restrict__ Xr, float* __restrict__ Xi) {
    float r00r = dt * A00r, r00i = dt * A00i;
    float r01r = dt * A01r, r01i = dt * A01i;
    float r10r = dt * A10r, r10i = dt * A10i;
    float r11r = dt * A11r, r11i = dt * A11i;
    float numr = r01r * r10r - r01i * r10i;
    float numi = r01r * r10i + r01i * r10r;
    float denr = 1.0f + r11r;
    float deni = r11i;
    float dd   = denr * denr + deni * deni;
    float dinv; asm("rcp.approx.f32 %0,%1;" : "=f"(dinv) : "f"(dd));
    float qr = (numr * denr + numi * deni) * dinv;
    float qi = (numi * denr - numr * deni) * dinv;
    float xr = r00r - qr;
    float xi = r00i - qi;
    Xr[f] = xr - xi * gi;      // * (1 + i*gi), gi = tan(pi f / L)
    Xi[f] = xr * gi + xi;
}

// ---------------------------------------------------------------------------
// Fused kernel, one block per h, 256 threads (single clean wave at 2 blk/SM).
// Phase 1: Cauchy + Woodbury (R4 inner loop: f32x2 lanes = n-pair, 4 freqs/thr).
// Phase 2: irfft(L=2048) via 1024-pt complex inverse FFT, two radix-2 stages
//   fused per smem round-trip (5 syncs instead of 10), smem twiddle table.
// ---------------------------------------------------------------------------
__global__ __launch_bounds__(TPB)
void fused_kernel(const float* __restrict__ Cin, const float* __restrict__ Bin,
                  const float* __restrict__ Pin, const float* __restrict__ Win,
                  const float* __restrict__ logdt, float* __restrict__ out) {
    // [const][n]: 0 wdi, 1 wdr2, 2 -wdr, 3 v00r, 4 v00i, 5 v01r, 6 v01i,
    //             7 v10r, 8 v10i, 9 v11r
    __shared__ __align__(16) float scn[10][NN];
    __shared__ float2 tw[MM / 2];            // e^{+2*pi*i*t/1024}
    __shared__ float Xr[FF + 3], Xi[FF + 3];
    __shared__ float2 Zc[MM];

    const int h   = blockIdx.x;
    const int tid = threadIdx.x;
    const float dt = expf(logdt[h]);

    // twiddle table: 2 entries per thread (one-time cost, overlaps setup)
#pragma unroll
    for (int j = 0; j < 2; j++) {
        int t = tid + 256 * j;
        float s, c;
        sincospif((float)t * (1.0f / 512.0f), &s, &c);
        tw[t] = make_float2(c, s);
    }

    if (tid < NN) {
        const int base = h * (NN * 2) + tid * 2;
        float cr = Cin[base], ci = Cin[base + 1];
        float br = Bin[base], bi = Bin[base + 1];
        float pr = Pin[base], pi = Pin[base + 1];
        float wr = Win[base], wi = Win[base + 1];
        float wdr = wr * dt, wdi = wi * dt;
        scn[0][tid] = wdi;
        scn[1][tid] = wdr * wdr;
        scn[2][tid] = -wdr;
        scn[3][tid] = br * cr - bi * ci;   // v00r = Re(B*C)
        scn[4][tid] = br * ci + bi * cr;   // v00i
        scn[5][tid] = br * pr + bi * pi;   // v01r = Re(B*conj(P))
        scn[6][tid] = bi * pr - br * pi;   // v01i
        scn[7][tid] = pr * cr - pi * ci;   // v10r = Re(P*C)
        scn[8][tid] = pr * ci + pi * cr;   // v10i
        scn[9][tid] = pr * pr + pi * pi;   // v11r = |P|^2 (real)
    }
    __syncthreads();

    // z_f = 2*i*tan(pi f / L); this thread's 4 freqs, duplicated into lanes
    float zis[4];
    uint64_t zi[4];
#pragma unroll
    for (int j = 0; j < 4; j++) {
        int f = tid + 256 * j;
        float s, c;
        sincospif((float)f * (1.0f / LL), &s, &c);
        zis[j] = 2.0f * __fdividef(s, c);
        zi[j] = pk2(zis[j], zis[j]);
    }

    uint64_t a00r[4], a00i[4], a01r[4], a01i[4];
    uint64_t a10r[4], a10i[4], a11r[4], a11i[4];
#pragma unroll
    for (int j = 0; j < 4; j++) {
        a00r[j] = a00i[j] = a01r[j] = a01i[j] = 0;
        a10r[j] = a10i[j] = a11r[j] = a11i[j] = 0;
    }

    const uint64_t* s0 = (const uint64_t*)&scn[0][0];
    const uint64_t* s1 = (const uint64_t*)&scn[1][0];
    const uint64_t* s2 = (const uint64_t*)&scn[2][0];
    const uint64_t* s3 = (const uint64_t*)&scn[3][0];
    const uint64_t* s4 = (const uint64_t*)&scn[4][0];
    const uint64_t* s5 = (const uint64_t*)&scn[5][0];
    const uint64_t* s6 = (const uint64_t*)&scn[6][0];
    const uint64_t* s7 = (const uint64_t*)&scn[7][0];
    const uint64_t* s8 = (const uint64_t*)&scn[8][0];
    const uint64_t* s9 = (const uint64_t*)&scn[9][0];

#pragma unroll 2
    for (int m = 0; m < NN / 2; m++) {       // n-pair index
        uint64_t wdi = s0[m], wdr2 = s1[m], nwdr = s2[m];
        uint64_t v00r = s3[m], v00i = s4[m];
        uint64_t v01r = s5[m], v01i = s6[m];
        uint64_t v10r = s7[m], v10i = s8[m];
        uint64_t v11r = s9[m];
#pragma unroll
        for (int j = 0; j < 4; j++) {
            // denom = -wdr + i*(zi - wdi); 1/denom = (-wdr - i*D)*inv
            uint64_t D   = sub2(zi[j], wdi);
            uint64_t den = fma2(D, D, wdr2);
            uint64_t inv = rcp2(den);
            uint64_t tr  = mul2(nwdr, inv);                  //  Re 1/denom
            uint64_t mti = mul2(D, inv);                     // -Im 1/denom
            uint64_t ti  = mti ^ 0x8000000080000000ULL;      //  Im (ALU pipe)
            a00r[j] = fma2(v00r, tr, a00r[j]); a00r[j] = fma2(v00i, mti, a00r[j]);
            a00i[j] = fma2(v00r, ti, a00i[j]); a00i[j] = fma2(v00i, tr,  a00i[j]);
            a01r[j] = fma2(v01r, tr, a01r[j]); a01r[j] = fma2(v01i, mti, a01r[j]);
            a01i[j] = fma2(v01r, ti, a01i[j]); a01i[j] = fma2(v01i, tr,  a01i[j]);
            a10r[j] = fma2(v10r, tr, a10r[j]); a10r[j] = fma2(v10i, mti, a10r[j]);
            a10i[j] = fma2(v10r, ti, a10i[j]); a10i[j] = fma2(v10i, tr,  a10i[j]);
            a11r[j] = fma2(v11r, tr, a11r[j]);
            a11i[j] = fma2(v11r, ti, a11i[j]);
        }
    }

    // Epilogue: lane-sum (over n halves), Woodbury, gain, write X to smem
#pragma unroll
    for (int j = 0; j < 4; j++) {
        int f = tid + 256 * j;
        woodbury(lanesum(a00r[j]), lanesum(a00i[j]),
                 lanesum(a01r[j]), lanesum(a01i[j]),
                 lanesum(a10r[j]), lanesum(a10i[j]),
                 lanesum(a11r[j]), lanesum(a11i[j]),
                 dt, 0.5f * zis[j], f, Xr, Xi);
    }

    // Nyquist bin f = L/2 (removable singularity): limit = 0.5*dt*sum_n v00r
    if (tid == 0) {
        float sr = 0.f;
        for (int n = 0; n < NN; n++) sr += scn[3][n];
        Xr[MM] = 0.5f * dt * sr;
        Xi[MM] = 0.f;
    }
    __syncthreads();

    // ---- Phase 2: irfft via 1024-pt complex inverse FFT ----
    // Build Z[k] = E[k] + i*O[k]
    const float scl = 1.0f / 2048.0f;
#pragma unroll
    for (int j = 0; j < 4; j++) {
        int k = tid + 256 * j;
        float Xkx = Xr[k],      Xky = Xi[k];
        float Xmx = Xr[MM - k], Xmy = Xi[MM - k];
        if (k == 0) { Xky = 0.f; Xmy = 0.f; }   // drop imag of DC & Nyquist
        float er  = (Xkx + Xmx) * scl;
        float ei  = (Xky - Xmy) * scl;
        float pr  = (Xkx - Xmx) * scl;
        float pi_ = (Xky + Xmy) * scl;
        float s, c;
        sincospif((float)k * (1.0f / MM), &s, &c);  // e^{+i*pi*k/1024}
        float Or = pr * c - pi_ * s;
        float Oi = pr * s + pi_ * c;
        Zc[k] = make_float2(er - Oi, ei + Or);      // Z = E + i*O
    }
    __syncthreads();

    // 10 radix-2 DIF stages executed as 5 fused double-stages.
    // q = quarter: thread owns closed group {g, g+q, g+2q, g+3q}.
#pragma unroll
    for (int q = 256; q >= 1; q >>= 2) {
        const int m = tid & (q - 1);
        const int g = ((tid - m) << 2) + m;
        const int t1 = m * (256 / q);            // stage-A twiddle index

        float2 a = Zc[g], b = Zc[g + q], c = Zc[g + 2 * q], d = Zc[g + 3 * q];

        // Stage A (half = 2q): pairs (a,c), (b,d)
        float2 w1 = tw[t1];
        float2 w2 = tw[t1 + 256];
        float2 t0v = cadd(a, c);
        float2 t1v = cmul(csub(a, c), w1);
        float2 t2v = cadd(b, d);
        float2 t3v = cmul(csub(b, d), w2);

        // Stage B (half = q): pairs (t0,t2) and (t1,t3), same twiddle
        float2 w3 = tw[m * (512 / q)];
        Zc[g]         = cadd(t0v, t2v);
        Zc[g + q]     = cmul(csub(t0v, t2v), w3);
        Zc[g + 2 * q] = cadd(t1v, t3v);
        Zc[g + 3 * q] = cmul(csub(t1v, t3v), w3);
        __syncthreads();
    }

    // de-interleave + bit-reversal permutation, vectorized float2 stores
    float2* out2 = reinterpret_cast<float2*>(out + h * LL);
#pragma unroll
    for (int j = 0; j < 4; j++) {
        int p = tid + 256 * j;
        int n = __brev((unsigned)p) >> 22;   // 10-bit reverse
        out2[n] = Zc[p];
    }
}

extern "C" void kernel_launch(void* const* d_in, const int* in_sizes, int n_in,
                              void* d_out, int out_size) {
    (void)in_sizes; (void)n_in; (void)out_size;
    const float* C  = (const float*)d_in[0];
    const float* B  = (const float*)d_in[1];
    const float* P  = (const float*)d_in[2];
    const float* W  = (const float*)d_in[3];
    const float* ld = (const float*)d_in[4];
    fused_kernel<<<HH, TPB>>>(C, B, P, W, ld, (float*)d_out);
}